// round 15
// baseline (speedup 1.0000x reference)
#include <cuda_runtime.h>
#include <math.h>

#define H 1024
#define NHD 8
#define DFF 4096
#define PLIN 256
#define CTX 2048
#define MAXHD 512
#define NL 15
#define NBLK 148
#define NTHR 1024
#define NW (NBLK * 32)

// ---------------- device state ----------------
__device__ float g_hbuf[2][H];
__device__ float g_qkv[10 * MAXHD];
__device__ float g_scores[NHD * CTX];
__device__ float g_prob[NHD * CTX];
__device__ float g_x[NHD * MAXHD];
__device__ float g_o[H];
__device__ float g_gu[2 * DFF];
__device__ float g_mlp[H];
__device__ float g_pg[PLIN];
__device__ float g_g2[H];
__device__ float g_vf[MAXHD];
__device__ float g_ksave[2][MAXHD];
__device__ float g_vsave[2][MAXHD];
__device__ unsigned g_pmax[NBLK * NHD];
__device__ float g_esum[NHD];
__device__ unsigned g_bar_count;
__device__ volatile unsigned g_bar_gen;

// ---------------- barrier ----------------
__device__ __forceinline__ void gsync() {
    __syncthreads();
    if (threadIdx.x == 0) {
        unsigned gen = g_bar_gen;
        __threadfence();
        if (atomicAdd(&g_bar_count, 1u) == NBLK - 1) {
            g_bar_count = 0;
            __threadfence();
            g_bar_gen = gen + 1;
        } else {
            while (g_bar_gen == gen) {}
            __threadfence();
        }
    }
    __syncthreads();
}

// ---------------- helpers ----------------
__device__ __forceinline__ float gelu_tanh(float x) {
    float x3 = x * x * x;
    return 0.5f * x * (1.f + tanhf(0.7978845608028654f * (x + 0.044715f * x3)));
}
__device__ __forceinline__ unsigned fenc(float f) {
    unsigned u = __float_as_uint(f);
    return (u & 0x80000000u) ? ~u : (u | 0x80000000u);
}
__device__ __forceinline__ float fdec(unsigned e) {
    unsigned u = (e & 0x80000000u) ? (e & 0x7fffffffu) : ~e;
    return __uint_as_float(u);
}
__device__ __forceinline__ void red3(float4& a) {
    #pragma unroll
    for (int off = 16; off >= 4; off >>= 1) {
        a.x += __shfl_down_sync(0xffffffffu, a.x, off);
        a.y += __shfl_down_sync(0xffffffffu, a.y, off);
        a.z += __shfl_down_sync(0xffffffffu, a.z, off);
        a.w += __shfl_down_sync(0xffffffffu, a.w, off);
    }
}
__device__ __forceinline__ float red32(float v) {
    #pragma unroll
    for (int off = 16; off; off >>= 1) v += __shfl_down_sync(0xffffffffu, v, off);
    return v;
}
__device__ float blockSum(float v) {
    __shared__ float red[32];
    int lane = threadIdx.x & 31, wid = threadIdx.x >> 5, nw = blockDim.x >> 5;
    __syncthreads();
    #pragma unroll
    for (int o = 16; o; o >>= 1) v += __shfl_down_sync(0xffffffffu, v, o);
    if (lane == 0) red[wid] = v;
    __syncthreads();
    float s = (threadIdx.x < nw) ? red[threadIdx.x] : 0.f;
    if (wid == 0) {
        #pragma unroll
        for (int o = 16; o; o >>= 1) s += __shfl_down_sync(0xffffffffu, s, o);
        if (lane == 0) red[0] = s;
    }
    __syncthreads();
    return red[0];
}

// ---------------- megakernel ----------------
__global__ void __launch_bounds__(NTHR, 1) megakernel(
    const float* __restrict__ embed, const float* __restrict__ cos_s, const float* __restrict__ sin_s,
    const float* __restrict__ cos_f, const float* __restrict__ sin_f,
    const float* __restrict__ ln_in, const float* __restrict__ ln_pa, const float* __restrict__ ln_pff,
    const float* __restrict__ ln_post, const float* __restrict__ ln_ppli,
    const float* __restrict__ qn_w, const float* __restrict__ kn_w,
    const float* __restrict__ Wq, const float* __restrict__ Wk, const float* __restrict__ Wv,
    const float* __restrict__ Wo, const float* __restrict__ Wg, const float* __restrict__ Wu,
    const float* __restrict__ Wd, const float* __restrict__ Wpg, const float* __restrict__ Wpp,
    const float* __restrict__ lsc, const float* __restrict__ kvc, const float* __restrict__ plc,
    const float* __restrict__ img, const float* __restrict__ mask,
    const int* __restrict__ ids, const int* __restrict__ posp,
    float* __restrict__ out)
{
    const int t = threadIdx.x;
    const int bid = blockIdx.x;
    const int w = t >> 5, lane = t & 31;
    const int gw = bid * 32 + w;
    const int c = lane & 3, r = lane >> 2;

    __shared__ float4 s_a4[1024];     // 4096 floats
    __shared__ float4 s_b4[256];      // 1024 floats
    __shared__ float4 s_c4[256];      // 1024 floats
    __shared__ float s_m[16];
    __shared__ unsigned s_bmax[8];
    float* s_a = (float*)s_a4;
    float* s_b = (float*)s_b4;
    float* s_c = (float*)s_c4;

    const int pos = posp[0];
    int cp = 0;

    // ===== init: zero accumulators =====
    if (bid == 0) { for (int i = t; i < 10 * MAXHD; i += NTHR) g_qkv[i] = 0.f; }
    if (bid == 1) { for (int i = t; i < NHD * MAXHD; i += NTHR) g_x[i] = 0.f; }
    if (bid == 2) { g_o[t] = 0.f; g_mlp[t] = 0.f; }
    if (bid == 3) { g_g2[t] = 0.f; if (t < PLIN) g_pg[t] = 0.f; if (t < NHD) g_esum[t] = 0.f; }
    if (bid == 4) { for (int i = t; i < 2 * DFF; i += NTHR) g_gu[i] = 0.f; }
    gsync();

    for (int l = 0; l < NL; l++) {
        const bool full = ((l + 1) % 5 == 0);
        const int hd = full ? 512 : 256;
        const int lhd = full ? 9 : 8;
        const int nq = NHD * hd;
        const float4* Wq4 = (const float4*)(Wq + (size_t)l * H * NHD * MAXHD);
        const float4* Wk4 = (const float4*)(Wk + (size_t)l * H * MAXHD);
        const float4* Wv4 = (const float4*)(Wv + (size_t)l * H * MAXHD);
        const float4* Wo4 = (const float4*)(Wo + (size_t)l * NHD * MAXHD * H);
        const float4* Wg4 = (const float4*)(Wg + (size_t)l * H * DFF);
        const float4* Wu4 = (const float4*)(Wu + (size_t)l * H * DFF);
        const float4* Wd4 = (const float4*)(Wd + (size_t)l * DFF * H);

        // ===== S1: preamble (finish_pli / init) + QKV warp-jobs =====
        {
            float hv;
            if (l == 0) {
                float a = fabsf(img[t]);
                float asum = blockSum(a);
                float is = (asum > 0.f) ? 1.f : 0.f;
                hv = embed[(size_t)ids[0] * H + t] * 32.0f * (1.f - is) + img[t] * is;
            } else {
                float g2 = g_g2[t];
                float ss = blockSum(g2 * g2);
                float sc = rsqrtf(ss / (float)H + 1e-6f);
                hv = (g_hbuf[cp][t] + g2 * sc * (1.f + ln_ppli[(size_t)(l - 1) * H + t])) * lsc[l - 1];
            }
            if (bid == 0) g_hbuf[cp ^ 1][t] = hv;
            float ss2 = blockSum(hv * hv);
            float sc2 = rsqrtf(ss2 / (float)H + 1e-6f);
            s_b[t] = hv * sc2 * (1.f + ln_in[(size_t)l * H + t]);
            __syncthreads();
            cp ^= 1;

            const int ngroups = (10 * hd) >> 4;          // 160 / 320
            const int njobs = ngroups << 4;              // ksegs=16 (kseg=64)
            for (int j = gw; j < njobs; j += NW) {
                int g = j % ngroups, ks = j / ngroups;
                int n0 = g << 4;
                const float4* W4; int ld4, col4;
                if (n0 < nq)            { W4 = Wq4; ld4 = 1024; col4 = ((n0 >> lhd) << 7) + ((n0 & (hd - 1)) >> 2); }
                else if (n0 < nq + hd)  { W4 = Wk4; ld4 = 128;  col4 = (n0 - nq) >> 2; }
                else                    { W4 = Wv4; ld4 = 128;  col4 = (n0 - nq - hd) >> 2; }
                int kbase = ks << 6;
                const float4* wp = W4 + (size_t)(kbase + r) * ld4 + col4 + c;
                float4 acc = make_float4(0.f, 0.f, 0.f, 0.f);
                #pragma unroll
                for (int i = 0; i < 8; i++) {
                    float xv = s_b[kbase + r + (i << 3)];
                    float4 wv = wp[(size_t)(i << 3) * ld4];
                    acc.x += xv * wv.x; acc.y += xv * wv.y; acc.z += xv * wv.z; acc.w += xv * wv.w;
                }
                red3(acc);
                if (lane < 4) {
                    int nb = n0 + (lane << 2);
                    atomicAdd(&g_qkv[nb + 0], acc.x);
                    atomicAdd(&g_qkv[nb + 1], acc.y);
                    atomicAdd(&g_qkv[nb + 2], acc.z);
                    atomicAdd(&g_qkv[nb + 3], acc.w);
                }
            }
        }
        gsync();

        // ===== S2: scores (rope/rms preamble; warp-per-token jobs) =====
        {
            if (t < 8) s_bmax[t] = 0u;
            if (w < 10) {
                float s = 0.f;
                for (int d = lane; d < hd; d += 32) { float x = g_qkv[w * hd + d]; s += x * x; }
                #pragma unroll
                for (int o = 16; o; o >>= 1) s += __shfl_down_sync(0xffffffffu, s, o);
                if (lane == 0) s_m[w] = rsqrtf(s / (float)hd + 1e-6f);
            }
            __syncthreads();
            const float* cr = (full ? cos_f : cos_s) + (size_t)pos * hd;
            const float* sr = (full ? sin_f : sin_s) + (size_t)pos * hd;
            const float* qw = qn_w + (size_t)l * MAXHD;
            const float* kw = kn_w + (size_t)l * MAXHD;
            int half = hd >> 1;
            for (int i = t; i < NHD * hd; i += NTHR) {
                int hh = i >> lhd, d = i & (hd - 1);
                float qs = s_m[hh];
                float x = g_qkv[hh * hd + d] * qs * (1.f + qw[d]);
                int pd = (d < half) ? d + half : d - half;
                float px = g_qkv[hh * hd + pd] * qs * (1.f + qw[pd]);
                float rr = (d < half) ? -px : px;
                s_a[i] = x * cr[d] + rr * sr[d];
            }
            if (t < hd) {
                int d = t;
                float ks = s_m[8];
                float x = g_qkv[8 * hd + d] * ks * (1.f + kw[d]);
                int pd = (d < half) ? d + half : d - half;
                float px = g_qkv[8 * hd + pd] * ks * (1.f + kw[pd]);
                float rr = (d < half) ? -px : px;
                float kf = x * cr[d] + rr * sr[d];
                s_b[d] = kf;
                float vf = g_qkv[9 * hd + d] * s_m[9];
                s_c[d] = vf;
                if (bid == 0) {
                    g_vf[d] = vf;
                    if (l == 13) { g_ksave[0][d] = kf; g_vsave[0][d] = vf; }
                    if (l == 14) { g_ksave[1][d] = kf; g_vsave[1][d] = vf; }
                }
            }
            __syncthreads();

            const float4* K4 = (const float4*)(kvc + (size_t)l * CTX * MAXHD);
            const int np = hd >> 7;
            for (int j = gw; j < CTX; j += NW) {
                int tt = j;
                if (tt > pos) {
                    if (lane < 8) g_scores[lane * CTX + tt] = mask[tt];
                    continue;
                }
                const float4* kr = (tt == pos) ? s_b4 : (K4 + (size_t)tt * 128);
                float acc[NHD];
                #pragma unroll
                for (int h = 0; h < NHD; h++) acc[h] = 0.f;
                for (int p = 0; p < np; p++) {
                    float4 kv = kr[lane + (p << 5)];
                    #pragma unroll
                    for (int h = 0; h < NHD; h++) {
                        float4 q = s_a4[h * (hd >> 2) + lane + (p << 5)];
                        acc[h] += kv.x * q.x + kv.y * q.y + kv.z * q.z + kv.w * q.w;
                    }
                }
                #pragma unroll
                for (int h = 0; h < NHD; h++) {
                    float a = red32(acc[h]);
                    if (lane == 0) {
                        float v = a + mask[tt];
                        g_scores[h * CTX + tt] = v;
                        atomicMax(&s_bmax[h], fenc(v));
                    }
                }
            }
            __syncthreads();
            if (t < 8) g_pmax[(bid << 3) + t] = s_bmax[t];
            if (gw == NW - 1 && lane < 8) g_esum[lane] = 0.f;
        }
        gsync();

        // ===== S3: prob (exp + esum) + zero g_x =====
        {
            for (int j = gw; j < 64; j += NW) {
                int t0 = j << 5;
                int tt = t0 + lane;
                float mh[NHD];
                #pragma unroll
                for (int h = 0; h < NHD; h++) {
                    unsigned mu = 0u;
                    for (int b = lane; b < NBLK; b += 32) mu = max(mu, g_pmax[(b << 3) + h]);
                    #pragma unroll
                    for (int o = 16; o; o >>= 1) mu = max(mu, __shfl_down_sync(0xffffffffu, mu, o));
                    mu = __shfl_sync(0xffffffffu, mu, 0);
                    mh[h] = fdec(mu);
                }
                #pragma unroll
                for (int h = 0; h < NHD; h++) {
                    float sco = g_scores[h * CTX + tt];
                    float e = __expf(sco - mh[h]);
                    g_prob[h * CTX + tt] = e;
                    float s = red32(e);
                    if (lane == 0) atomicAdd(&g_esum[h], s);
                }
            }
            if (gw >= NW - 32) {
                int f4i = (gw - (NW - 32)) * 32 + lane;
                ((float4*)g_x)[f4i] = make_float4(0.f, 0.f, 0.f, 0.f);
            }
        }
        gsync();

        // ===== S4: AV warp-jobs (+ zero g_o) =====
        {
            const int nDG = hd >> 4;                     // 16 / 32
            const int njobs = nDG * 32 * 2;
            const float4* V4 = (const float4*)(kvc + (size_t)(NL + l) * CTX * MAXHD);
            const float4* vf4 = (const float4*)g_vf;
            for (int j = gw; j < njobs; j += NW) {
                int dg = j % nDG;
                int rest = j / nDG;
                int seg = rest & 31, hh = rest >> 5;
                int t0 = seg << 6;
                if (t0 > pos) continue;
                int h0 = hh << 2;
                float4 a0 = make_float4(0.f,0.f,0.f,0.f), a1 = a0, a2 = a0, a3 = a0;
                #pragma unroll
                for (int i = 0; i < 8; i++) {
                    int tt = t0 + r + (i << 3);
                    const float4* vr = (tt == pos) ? vf4 : (V4 + (size_t)tt * 128);
                    float4 v = vr[(dg << 2) + c];
                    float p0 = g_prob[(h0 + 0) * CTX + tt];
                    float p1 = g_prob[(h0 + 1) * CTX + tt];
                    float p2 = g_prob[(h0 + 2) * CTX + tt];
                    float p3 = g_prob[(h0 + 3) * CTX + tt];
                    a0.x += p0*v.x; a0.y += p0*v.y; a0.z += p0*v.z; a0.w += p0*v.w;
                    a1.x += p1*v.x; a1.y += p1*v.y; a1.z += p1*v.z; a1.w += p1*v.w;
                    a2.x += p2*v.x; a2.y += p2*v.y; a2.z += p2*v.z; a2.w += p2*v.w;
                    a3.x += p3*v.x; a3.y += p3*v.y; a3.z += p3*v.z; a3.w += p3*v.w;
                }
                red3(a0); red3(a1); red3(a2); red3(a3);
                if (lane < 4) {
                    int db = (dg << 4) + (lane << 2);
                    float* x0 = &g_x[(h0 + 0) * hd + db];
                    float* x1 = &g_x[(h0 + 1) * hd + db];
                    float* x2 = &g_x[(h0 + 2) * hd + db];
                    float* x3 = &g_x[(h0 + 3) * hd + db];
                    atomicAdd(x0+0,a0.x); atomicAdd(x0+1,a0.y); atomicAdd(x0+2,a0.z); atomicAdd(x0+3,a0.w);
                    atomicAdd(x1+0,a1.x); atomicAdd(x1+1,a1.y); atomicAdd(x1+2,a1.z); atomicAdd(x1+3,a1.w);
                    atomicAdd(x2+0,a2.x); atomicAdd(x2+1,a2.y); atomicAdd(x2+2,a2.z); atomicAdd(x2+3,a2.w);
                    atomicAdd(x3+0,a3.x); atomicAdd(x3+1,a3.y); atomicAdd(x3+2,a3.z); atomicAdd(x3+3,a3.w);
                }
            }
            if (gw == NW - 1) {
                for (int i = lane; i < 256; i += 32) ((float4*)g_o)[i] = make_float4(0.f,0.f,0.f,0.f);
            }
        }
        gsync();

        // ===== S5: O gemv =====
        {
            if (t < 8) s_m[t] = 1.f / g_esum[t];
            __syncthreads();
            for (int i = t; i < nq; i += NTHR) s_a[i] = g_x[i] * s_m[i >> lhd];
            __syncthreads();
            const int ksegs = nq >> 7;                   // 16 / 32
            const int njobs = ksegs << 6;
            for (int j = gw; j < njobs; j += NW) {
                int g = j & 63, ks = j >> 6;
                int n0 = g << 4;
                int kbase = ks << 7;
                float4 acc = make_float4(0.f,0.f,0.f,0.f);
                #pragma unroll
                for (int i = 0; i < 16; i++) {
                    int k = kbase + r + (i << 3);
                    int row = ((k >> lhd) << 9) + (k & (hd - 1));
                    float4 wv = Wo4[(size_t)row * 256 + (g << 2) + c];
                    float xv = s_a[k];
                    acc.x += xv*wv.x; acc.y += xv*wv.y; acc.z += xv*wv.z; acc.w += xv*wv.w;
                }
                red3(acc);
                if (lane < 4) {
                    int nb = n0 + (lane << 2);
                    atomicAdd(&g_o[nb+0], acc.x); atomicAdd(&g_o[nb+1], acc.y);
                    atomicAdd(&g_o[nb+2], acc.z); atomicAdd(&g_o[nb+3], acc.w);
                }
            }
        }
        gsync();

        // ===== S6: GU gemv (+finish_o preamble; + zero g_mlp) =====
        {
            float o = g_o[t];
            float ss = blockSum(o * o);
            float sc = rsqrtf(ss / (float)H + 1e-6f);
            float hv = g_hbuf[cp][t] + o * sc * (1.f + ln_pa[(size_t)l * H + t]);
            if (bid == 0) g_hbuf[cp ^ 1][t] = hv;
            float ss2 = blockSum(hv * hv);
            float sc2 = rsqrtf(ss2 / (float)H + 1e-6f);
            s_b[t] = hv * sc2 * (1.f + ln_pff[(size_t)l * H + t]);
            __syncthreads();
            cp ^= 1;
            const int njobs = 512 * 8;                   // kseg=128
            for (int j = gw; j < njobs; j += NW) {
                int g = j & 511, ks = j >> 9;
                int n0 = g << 4;
                const float4* W4 = (n0 < DFF) ? Wg4 : Wu4;
                int col4 = ((n0 < DFF) ? n0 : (n0 - DFF)) >> 2;
                int kbase = ks << 7;
                const float4* wp = W4 + (size_t)(kbase + r) * 1024 + col4 + c;
                float4 acc = make_float4(0.f,0.f,0.f,0.f);
                #pragma unroll
                for (int i = 0; i < 16; i++) {
                    float xv = s_b[kbase + r + (i << 3)];
                    float4 wv = wp[(size_t)(i << 3) * 1024];
                    acc.x += xv*wv.x; acc.y += xv*wv.y; acc.z += xv*wv.z; acc.w += xv*wv.w;
                }
                red3(acc);
                if (lane < 4) {
                    int nb = n0 + (lane << 2);
                    atomicAdd(&g_gu[nb+0], acc.x); atomicAdd(&g_gu[nb+1], acc.y);
                    atomicAdd(&g_gu[nb+2], acc.z); atomicAdd(&g_gu[nb+3], acc.w);
                }
            }
            if (gw == 4700) {
                for (int i = lane; i < 256; i += 32) ((float4*)g_mlp)[i] = make_float4(0.f,0.f,0.f,0.f);
            }
        }
        gsync();

        // ===== S7: down gemv (gelu·up preamble; + zero g_pg) =====
        {
            for (int i = t; i < DFF; i += NTHR) s_a[i] = gelu_tanh(g_gu[i]) * g_gu[DFF + i];
            __syncthreads();
            const int njobs = 64 * 32;                   // kseg=128
            for (int j = gw; j < njobs; j += NW) {
                int g = j & 63, ks = j >> 6;
                int n0 = g << 4;
                int kbase = ks << 7;
                const float4* wp = Wd4 + (size_t)(kbase + r) * 256 + (g << 2) + c;
                float4 acc = make_float4(0.f,0.f,0.f,0.f);
                #pragma unroll
                for (int i = 0; i < 16; i++) {
                    float xv = s_a[kbase + r + (i << 3)];
                    float4 wv = wp[(size_t)(i << 3) * 256];
                    acc.x += xv*wv.x; acc.y += xv*wv.y; acc.z += xv*wv.z; acc.w += xv*wv.w;
                }
                red3(acc);
                if (lane < 4) {
                    int nb = n0 + (lane << 2);
                    atomicAdd(&g_mlp[nb+0], acc.x); atomicAdd(&g_mlp[nb+1], acc.y);
                    atomicAdd(&g_mlp[nb+2], acc.z); atomicAdd(&g_mlp[nb+3], acc.w);
                }
            }
            if (gw == 4700) {
                for (int i = lane; i < 64; i += 32) ((float4*)g_pg)[i] = make_float4(0.f,0.f,0.f,0.f);
            }
        }
        gsync();

        // ===== S8: PG gemv (+finish_ff preamble; + zero g_g2, zero g_gu) =====
        {
            float m = g_mlp[t];
            float ss = blockSum(m * m);
            float sc = rsqrtf(ss / (float)H + 1e-6f);
            float hv = g_hbuf[cp][t] + m * sc * (1.f + ln_post[(size_t)l * H + t]);
            if (bid == 0) g_hbuf[cp ^ 1][t] = hv;
            s_b[t] = hv;
            __syncthreads();
            cp ^= 1;
            const float4* Wpg4 = (const float4*)(Wpg + (size_t)l * H * PLIN);
            const int njobs = 16 * 16;                   // kseg=64
            for (int j = gw; j < njobs; j += NW) {
                int g = j & 15, ks = j >> 4;
                int n0 = g << 4;
                int kbase = ks << 6;
                const float4* wp = Wpg4 + (size_t)(kbase + r) * 64 + (g << 2) + c;
                float4 acc = make_float4(0.f,0.f,0.f,0.f);
                #pragma unroll
                for (int i = 0; i < 8; i++) {
                    float xv = s_b[kbase + r + (i << 3)];
                    float4 wv = wp[(size_t)(i << 3) * 64];
                    acc.x += xv*wv.x; acc.y += xv*wv.y; acc.z += xv*wv.z; acc.w += xv*wv.w;
                }
                red3(acc);
                if (lane < 4) {
                    int nb = n0 + (lane << 2);
                    atomicAdd(&g_pg[nb+0], acc.x); atomicAdd(&g_pg[nb+1], acc.y);
                    atomicAdd(&g_pg[nb+2], acc.z); atomicAdd(&g_pg[nb+3], acc.w);
                }
            }
            // zero g_gu (2048 float4) — consumed by all blocks in S7 preamble; safe after S7→S8 gsync
            if (gw >= 512 && gw < 576) {
                int f4i = (gw - 512) * 32 + lane;
                ((float4*)g_gu)[f4i] = make_float4(0.f,0.f,0.f,0.f);
            }
            if (gw == 4700) {
                for (int i = lane; i < 256; i += 32) ((float4*)g_g2)[i] = make_float4(0.f,0.f,0.f,0.f);
            }
        }
        gsync();

        // ===== S9: PP gemv (gelu·pls preamble; + zero g_qkv) =====
        {
            const float* pls = plc + (size_t)l * PLIN;
            if (t < PLIN) s_c[t] = gelu_tanh(g_pg[t]) * pls[t];
            __syncthreads();
            const float4* Wpp4 = (const float4*)(Wpp + (size_t)l * PLIN * H);
            const int njobs = 64 * 4;                    // kseg=64
            for (int j = gw; j < njobs; j += NW) {
                int g = j & 63, ks = j >> 6;
                int n0 = g << 4;
                int kbase = ks << 6;
                const float4* wp = Wpp4 + (size_t)(kbase + r) * 256 + (g << 2) + c;
                float4 acc = make_float4(0.f,0.f,0.f,0.f);
                #pragma unroll
                for (int i = 0; i < 8; i++) {
                    float xv = s_c[kbase + r + (i << 3)];
                    float4 wv = wp[(size_t)(i << 3) * 256];
                    acc.x += xv*wv.x; acc.y += xv*wv.y; acc.z += xv*wv.z; acc.w += xv*wv.w;
                }
                red3(acc);
                if (lane < 4) {
                    int nb = n0 + (lane << 2);
                    atomicAdd(&g_g2[nb+0], acc.x); atomicAdd(&g_g2[nb+1], acc.y);
                    atomicAdd(&g_g2[nb+2], acc.z); atomicAdd(&g_g2[nb+3], acc.w);
                }
            }
            if (gw >= 4704 && gw < 4714) {
                int base = (gw - 4704) * 128;
                #pragma unroll
                for (int q = 0; q < 4; q++)
                    ((float4*)g_qkv)[base + (q << 5) + lane] = make_float4(0.f,0.f,0.f,0.f);
            }
        }
        gsync();
    }

    // ===== epilogue =====
    if (bid == 0) {
        float g2 = g_g2[t];
        float ss = blockSum(g2 * g2);
        float sc = rsqrtf(ss / (float)H + 1e-6f);
        float hv = (g_hbuf[cp][t] + g2 * sc * (1.f + ln_ppli[(size_t)(NL - 1) * H + t])) * lsc[NL - 1];
        out[t] = hv;
    }
    {
        float4* out4 = (float4*)(out + 1024);
        const float4* kvc4 = (const float4*)kvc;
        for (int i = bid * NTHR + t; i < 786432; i += NBLK * NTHR) {
            float4 val;
            if (i < 131072) {
                int tt = i >> 6, d4 = i & 63;
                val = (tt == pos) ? ((const float4*)g_ksave[0])[d4]
                                  : kvc4[((((size_t)13 * CTX + tt) * MAXHD) >> 2) + d4];
            } else if (i < 262144) {
                int j = i - 131072; int tt = j >> 6, d4 = j & 63;
                val = (tt == pos) ? ((const float4*)g_vsave[0])[d4]
                                  : kvc4[((((size_t)(NL + 13) * CTX + tt) * MAXHD) >> 2) + d4];
            } else if (i < 524288) {
                int j = i - 262144; int tt = j >> 7, d4 = j & 127;
                val = (tt == pos) ? ((const float4*)g_ksave[1])[d4]
                                  : kvc4[((((size_t)14 * CTX + tt) * MAXHD) >> 2) + d4];
            } else {
                int j = i - 524288; int tt = j >> 7, d4 = j & 127;
                val = (tt == pos) ? ((const float4*)g_vsave[1])[d4]
                                  : kvc4[((((size_t)(NL + 14) * CTX + tt) * MAXHD) >> 2) + d4];
            }
            out4[i] = val;
        }
    }
}

// ---------------- host ----------------
extern "C" void kernel_launch(void* const* d_in, const int* in_sizes, int n_in,
                              void* d_out, int out_size) {
    megakernel<<<NBLK, NTHR>>>(
        (const float*)d_in[0], (const float*)d_in[1], (const float*)d_in[2],
        (const float*)d_in[3], (const float*)d_in[4], (const float*)d_in[5],
        (const float*)d_in[6], (const float*)d_in[7], (const float*)d_in[8],
        (const float*)d_in[9], (const float*)d_in[10], (const float*)d_in[11],
        (const float*)d_in[12], (const float*)d_in[13], (const float*)d_in[14],
        (const float*)d_in[15], (const float*)d_in[16], (const float*)d_in[17],
        (const float*)d_in[18], (const float*)d_in[19], (const float*)d_in[20],
        (const float*)d_in[21], (const float*)d_in[22], (const float*)d_in[23],
        (const float*)d_in[24], (const float*)d_in[25],
        (const int*)d_in[27], (const int*)d_in[28],
        (float*)d_out);
}